// round 7
// baseline (speedup 1.0000x reference)
#include <cuda_runtime.h>
#include <cstdint>

#define Bz 128
#define Sz 64
#define Ez 300
#define Hz 512
#define Lz 5
#define GXW 1536   // 3*H : i, f, u x-side preactivations

// ---- device scratch (no allocation allowed) --------------------------------
__device__ float g_Gx  [(size_t)Bz * Sz * GXW];   // x-side gate preacts (+x bias)
__device__ float g_allH[(size_t)Bz * Sz * Hz];
__device__ float g_allC[(size_t)Bz * Sz * Hz];
__device__ float g_WfhH[(size_t)Bz * Sz * Hz];    // cache: Wfh @ allH[b,s] (no bias)
__device__ float g_hsum[Bz * Hz];
__device__ float g_hprev[Bz * Hz];
__device__ float g_y[Bz * 4 * Hz];                // [b][{yi,yo,yu,y4}][h]
__device__ unsigned long long g_procmask[Bz];

// ---- f32x2 packed FMA helpers ----------------------------------------------
static __device__ __forceinline__ unsigned long long pk2(float x, float y) {
    unsigned long long r;
    asm("mov.b64 %0, {%1, %2};" : "=l"(r) : "f"(x), "f"(y));
    return r;
}
static __device__ __forceinline__ unsigned long long fma2(unsigned long long a,
                                                          unsigned long long b,
                                                          unsigned long long c) {
    unsigned long long d;
    asm("fma.rn.f32x2 %0, %1, %2, %3;" : "=l"(d) : "l"(a), "l"(b), "l"(c));
    return d;
}
static __device__ __forceinline__ float2 upk2(unsigned long long v) {
    float lo, hi;
    asm("mov.b64 {%0, %1}, %2;" : "=f"(lo), "=f"(hi) : "l"(v));
    return make_float2(lo, hi);
}
static __device__ __forceinline__ float sigm(float z) {
    return 1.0f / (1.0f + expf(-z));
}

// ---- P0: zero recurrent state ----------------------------------------------
__global__ void k_init() {
    const size_t n = (size_t)Bz * Sz * Hz;
    const size_t stride = (size_t)gridDim.x * blockDim.x;
    size_t i = (size_t)blockIdx.x * blockDim.x + threadIdx.x;
    for (size_t j = i; j < n; j += stride) {
        g_allH[j] = 0.f; g_allC[j] = 0.f; g_WfhH[j] = 0.f;
    }
    for (size_t j = i; j < (size_t)Bz * Hz; j += stride) {
        g_hsum[j] = 0.f; g_hprev[j] = 0.f;
    }
    if (i < Bz) g_procmask[i] = 0ull;
}

// ---- P1: Gx = embed[x] @ {Wix,Wfx,Wux}^T + bias  ([8192,300]x[300,1536]) ---
__global__ __launch_bounds__(256) void k_precompute(
    const int* __restrict__ x, const float* __restrict__ embed,
    const float* __restrict__ Wix, const float* __restrict__ bix,
    const float* __restrict__ Wfx, const float* __restrict__ bfx,
    const float* __restrict__ Wux, const float* __restrict__ bux)
{
    const int nt = blockIdx.x;            // 0..23
    const int mt = blockIdx.y;            // 0..127
    const int g  = nt >> 3;               // gate 0=i,1=f,2=u
    const int jbase = (nt & 7) * 64;
    const float* W    = (g == 0) ? Wix : (g == 1) ? Wfx : Wux;
    const float* bias = (g == 0) ? bix : (g == 1) ? bfx : bux;
    const int tid = threadIdx.x;

    __shared__ int wid[64];
    __shared__ __align__(16) float As[16][64];
    __shared__ __align__(16) float Bs[16][64];

    const int rowbase = mt * 64;
    if (tid < 64) wid[tid] = x[rowbase + tid];
    __syncthreads();

    const int sm  = tid >> 2;   // 0..63
    const int skq = tid & 3;    // 0..3
    const int tm  = tid >> 4;   // 0..15 -> rows tm*4..+3
    const int tn  = tid & 15;   //        -> cols tn*4..+3

    unsigned long long acc[4][2];
#pragma unroll
    for (int r = 0; r < 4; r++) { acc[r][0] = 0ull; acc[r][1] = 0ull; }

    for (int kc = 0; kc < 19; kc++) {     // 19*16 = 304 >= 300
        const int k = kc * 16 + skq * 4;
        float4 va = make_float4(0.f,0.f,0.f,0.f), vb = va;
        if (k < Ez) {
            va = *reinterpret_cast<const float4*>(&embed[(size_t)wid[sm] * Ez + k]);
            vb = *reinterpret_cast<const float4*>(&W[(size_t)(jbase + sm) * Ez + k]);
        }
        As[skq*4+0][sm]=va.x; As[skq*4+1][sm]=va.y; As[skq*4+2][sm]=va.z; As[skq*4+3][sm]=va.w;
        Bs[skq*4+0][sm]=vb.x; Bs[skq*4+1][sm]=vb.y; Bs[skq*4+2][sm]=vb.z; Bs[skq*4+3][sm]=vb.w;
        __syncthreads();
#pragma unroll
        for (int kk = 0; kk < 16; kk++) {
            const float4 a4 = *reinterpret_cast<const float4*>(&As[kk][tm * 4]);
            const ulonglong2 bv = *reinterpret_cast<const ulonglong2*>(&Bs[kk][tn * 4]);
            const unsigned long long a0 = pk2(a4.x, a4.x);
            const unsigned long long a1 = pk2(a4.y, a4.y);
            const unsigned long long a2 = pk2(a4.z, a4.z);
            const unsigned long long a3 = pk2(a4.w, a4.w);
            acc[0][0]=fma2(a0,bv.x,acc[0][0]); acc[0][1]=fma2(a0,bv.y,acc[0][1]);
            acc[1][0]=fma2(a1,bv.x,acc[1][0]); acc[1][1]=fma2(a1,bv.y,acc[1][1]);
            acc[2][0]=fma2(a2,bv.x,acc[2][0]); acc[2][1]=fma2(a2,bv.y,acc[2][1]);
            acc[3][0]=fma2(a3,bv.x,acc[3][0]); acc[3][1]=fma2(a3,bv.y,acc[3][1]);
        }
        __syncthreads();
    }

    const int j = jbase + tn * 4;
#pragma unroll
    for (int r = 0; r < 4; r++) {
        const int row = rowbase + tm * 4 + r;
        float* dst = &g_Gx[(size_t)row * GXW + g * Hz + j];
        const float2 p0 = upk2(acc[r][0]);
        const float2 p1 = upk2(acc[r][1]);
        dst[0] = p0.x + bias[j+0]; dst[1] = p0.y + bias[j+1];
        dst[2] = p1.x + bias[j+2]; dst[3] = p1.y + bias[j+3];
    }
}

// ---- K2: per-step GEMM  [128,512]x[512,2048] -------------------------------
// y[b, g*512+j]: g0: hsum@Wih^T  g1: hsum@Wfh^T  g2: hsum@Wuh^T  g3: hprev@Wfh^T
__global__ __launch_bounds__(256) void k_stepgemm(
    const float* __restrict__ Wih, const float* __restrict__ Wfh,
    const float* __restrict__ Wuh)
{
    const int nt = blockIdx.x;           // 0..31
    const int mt = blockIdx.y;           // 0..3
    const int g  = nt >> 3;              // 0..3
    const int jbase = (nt & 7) * 64;
    const float* W = (g == 0) ? Wih : (g == 2) ? Wuh : Wfh;
    const float* A = (g == 3) ? g_hprev : g_hsum;
    const int m0 = mt * 32;
    const int tid = threadIdx.x;

    __shared__ __align__(16) float As[32][32];
    __shared__ __align__(16) float Bs[32][64];

    const int tm = tid >> 4;   // 0..15 -> rows tm*2, tm*2+1
    const int tn = tid & 15;   //        -> cols tn*4..+3
    unsigned long long acc[4] = {0ull, 0ull, 0ull, 0ull};

    for (int kc = 0; kc < 16; kc++) {
        const int k0 = kc * 32;
        {
            const int m = tid >> 3, kq = tid & 7;
            const float4 v = *reinterpret_cast<const float4*>(&A[(m0+m)*Hz + k0 + kq*4]);
            As[kq*4+0][m]=v.x; As[kq*4+1][m]=v.y; As[kq*4+2][m]=v.z; As[kq*4+3][m]=v.w;

            const int n = tid >> 2, kq2 = tid & 3;
            const size_t wb = (size_t)(jbase + n) * Hz + k0;
            const float4 w0 = *reinterpret_cast<const float4*>(&W[wb + kq2*4]);
            const float4 w1 = *reinterpret_cast<const float4*>(&W[wb + 16 + kq2*4]);
            Bs[kq2*4+0][n]=w0.x; Bs[kq2*4+1][n]=w0.y; Bs[kq2*4+2][n]=w0.z; Bs[kq2*4+3][n]=w0.w;
            Bs[16+kq2*4+0][n]=w1.x; Bs[16+kq2*4+1][n]=w1.y;
            Bs[16+kq2*4+2][n]=w1.z; Bs[16+kq2*4+3][n]=w1.w;
        }
        __syncthreads();
#pragma unroll
        for (int kk = 0; kk < 32; kk++) {
            const unsigned long long a2 =
                *reinterpret_cast<const unsigned long long*>(&As[kk][tm * 2]);
            const float4 b4 = *reinterpret_cast<const float4*>(&Bs[kk][tn * 4]);
            acc[0] = fma2(a2, pk2(b4.x, b4.x), acc[0]);
            acc[1] = fma2(a2, pk2(b4.y, b4.y), acc[1]);
            acc[2] = fma2(a2, pk2(b4.z, b4.z), acc[2]);
            acc[3] = fma2(a2, pk2(b4.w, b4.w), acc[3]);
        }
        __syncthreads();
    }

    const int r0 = m0 + tm * 2;
    const int cbase = g * Hz + jbase + tn * 4;
#pragma unroll
    for (int c = 0; c < 4; c++) {
        const float2 p = upk2(acc[c]);
        g_y[(size_t)r0 * 2048 + cbase + c]       = p.x;
        g_y[(size_t)(r0 + 1) * 2048 + cbase + c] = p.y;
    }
}

// ---- K3: gates + state update + next-step h_sum ----------------------------
__global__ __launch_bounds__(Hz) void k_gates(
    const int* __restrict__ bfs, const int* __restrict__ children,
    const float* __restrict__ bih, const float* __restrict__ bfh,
    const float* __restrict__ buh, int t)
{
    const int b = blockIdx.x;
    const int h = threadIdx.x;          // 0..511

    __shared__ int s_cur, s_prev, s_nxt, n0, n1;
    __shared__ unsigned long long s_bits;
    __shared__ unsigned char m0[Sz], m1[Sz];
    __shared__ short l0[Sz], l1[Sz];

    if (h == 0) {
        s_cur  = bfs[b * Sz + t];
        s_prev = (t > 0)      ? bfs[b * Sz + t - 1] : -1;
        s_nxt  = (t < Sz - 1) ? bfs[b * Sz + t + 1] : -1;
        s_bits = g_procmask[b];
    }
    __syncthreads();
    const int cur = s_cur, prev = s_prev, nxt = s_nxt;
    const unsigned long long bits = s_bits;

    if (h < Sz)
        m0[h] = (unsigned char)(children[((size_t)b * Sz + cur) * Sz + h] != 0);
    if (nxt >= 0 && h >= Sz && h < 2 * Sz)
        m1[h - Sz] = (unsigned char)(children[((size_t)b * Sz + nxt) * Sz + (h - Sz)] != 0);
    __syncthreads();

    if (h == 0) {
        int c0 = 0, c1 = 0;
        const unsigned long long b2 = bits | (1ull << cur);
        for (int s = 0; s < Sz; s++) {
            if (m0[s] && ((bits >> s) & 1ull)) l0[c0++] = (short)s;
            if (nxt >= 0 && m1[s] && ((b2 >> s) & 1ull)) l1[c1++] = (short)s;
        }
        n0 = c0; n1 = c1;
        g_procmask[b] = b2;
    }
    __syncthreads();

    const float* gx = &g_Gx[(size_t)(b * Sz + cur) * GXW];
    const float gxi = gx[h], gxf = gx[Hz + h], gxu = gx[2 * Hz + h];

    const float* yb = &g_y[(size_t)b * 2048];
    const float yi = yb[h], yo = yb[Hz + h], yu = yb[2 * Hz + h], y4 = yb[3 * Hz + h];

    const float vbfh = bfh[h];
    const float ig = sigm(gxi + yi + bih[h]);
    const float og = sigm(gxf + yo + vbfh);       // faithful: 'o' uses fx/fh weights
    const float ug = tanhf(gxu + yu + buh[h]);

    const float base = gxf + vbfh;
    const size_t bh = (size_t)b * Sz * Hz + h;

    float fc = 0.f;
    for (int i2 = 0; i2 < n0; i2++) {
        const int s = l0[i2];
        const float wf = (s == prev) ? y4 : g_WfhH[bh + (size_t)s * Hz];
        fc += sigm(wf + base) * g_allC[bh + (size_t)s * Hz];
    }

    const float cc = ig * ug + fc;
    const float hn = og * tanhf(cc);

    g_allC[bh + (size_t)cur * Hz] = cc;
    g_allH[bh + (size_t)cur * Hz] = hn;
    if (prev >= 0) g_WfhH[bh + (size_t)prev * Hz] = y4;
    g_hprev[b * Hz + h] = hn;

    if (nxt >= 0) {
        float hs = 0.f;
        for (int i2 = 0; i2 < n1; i2++) {
            const int s = l1[i2];
            hs += (s == cur) ? hn : g_allH[bh + (size_t)s * Hz];
        }
        g_hsum[b * Hz + h] = hs;
    }
}

// ---- K4: out = h_last @ Wout^T + bout  ([128,5]) ---------------------------
__global__ __launch_bounds__(160) void k_out(
    const float* __restrict__ Wout, const float* __restrict__ bout,
    float* __restrict__ out)
{
    const int b = blockIdx.x;
    const int w = threadIdx.x >> 5;     // 0..4 -> output label
    const int lane = threadIdx.x & 31;
    float p = 0.f;
    for (int hh = lane; hh < Hz; hh += 32)
        p += g_hprev[b * Hz + hh] * Wout[w * Hz + hh];
#pragma unroll
    for (int o = 16; o; o >>= 1) p += __shfl_down_sync(0xffffffffu, p, o);
    if (lane == 0) out[b * Lz + w] = p + bout[w];
}

// ---- launch ----------------------------------------------------------------
extern "C" void kernel_launch(void* const* d_in, const int* in_sizes, int n_in,
                              void* d_out, int out_size) {
    const int*   x        = (const int*)d_in[0];
    const int*   bfs      = (const int*)d_in[1];
    const int*   children = (const int*)d_in[2];
    const float* embed    = (const float*)d_in[3];
    const float* Wix = (const float*)d_in[4],  *bix = (const float*)d_in[5];
    const float* Wih = (const float*)d_in[6],  *bih = (const float*)d_in[7];
    const float* Wfx = (const float*)d_in[8],  *bfx = (const float*)d_in[9];
    const float* Wfh = (const float*)d_in[10], *bfh = (const float*)d_in[11];
    const float* Wux = (const float*)d_in[12], *bux = (const float*)d_in[13];
    const float* Wuh = (const float*)d_in[14], *buh = (const float*)d_in[15];
    const float* Wout = (const float*)d_in[16], *bout = (const float*)d_in[17];
    float* out = (float*)d_out;

    k_init<<<1024, 256>>>();
    k_precompute<<<dim3(24, 128), 256>>>(x, embed, Wix, bix, Wfx, bfx, Wux, bux);
    for (int t = 0; t < Sz; t++) {
        k_stepgemm<<<dim3(32, 4), 256>>>(Wih, Wfh, Wuh);
        k_gates<<<Bz, Hz>>>(bfs, children, bih, bfh, buh, t);
    }
    k_out<<<Bz, 160>>>(Wout, bout, out);
}

// round 9
// speedup vs baseline: 1.1938x; 1.1938x over previous
#include <cuda_runtime.h>
#include <cstdint>

#define Bz 128
#define Sz 64
#define Ez 300
#define Hz 512
#define Lz 5
#define GXW 1536   // 3*H : i, f, u x-side preactivations
#define NBLK 128
#define NTHR 512

// ---- device scratch (no allocation allowed) --------------------------------
__device__ float g_Gx  [(size_t)Bz * Sz * GXW];
__device__ float g_allH[(size_t)Bz * Sz * Hz];
__device__ float g_allC[(size_t)Bz * Sz * Hz];
__device__ float g_WfhH[(size_t)Bz * Sz * Hz];    // cache: Wfh @ allH[b,s]
__device__ float g_hsum[Bz * Hz];
__device__ float g_hprev[Bz * Hz];
__device__ float g_y[Bz * 4 * Hz];                // [b][{yi,yo,yu,y4}][h]
__device__ unsigned int g_bar_count;
__device__ unsigned int g_bar_gen;

// ---- f32x2 packed FMA helpers ----------------------------------------------
static __device__ __forceinline__ unsigned long long pk2(float x, float y) {
    unsigned long long r;
    asm("mov.b64 %0, {%1, %2};" : "=l"(r) : "f"(x), "f"(y));
    return r;
}
static __device__ __forceinline__ unsigned long long fma2(unsigned long long a,
                                                          unsigned long long b,
                                                          unsigned long long c) {
    unsigned long long d;
    asm("fma.rn.f32x2 %0, %1, %2, %3;" : "=l"(d) : "l"(a), "l"(b), "l"(c));
    return d;
}
static __device__ __forceinline__ float2 upk2(unsigned long long v) {
    float lo, hi;
    asm("mov.b64 {%0, %1}, %2;" : "=f"(lo), "=f"(hi) : "l"(v));
    return make_float2(lo, hi);
}
static __device__ __forceinline__ float sigm(float z) {
    return 1.0f / (1.0f + expf(-z));
}

// ---- P0: zero recurrent state + barrier vars -------------------------------
__global__ void k_init() {
    const size_t n = (size_t)Bz * Sz * Hz;
    const size_t stride = (size_t)gridDim.x * blockDim.x;
    size_t i = (size_t)blockIdx.x * blockDim.x + threadIdx.x;
    for (size_t j = i; j < n; j += stride) {
        g_allH[j] = 0.f; g_allC[j] = 0.f; g_WfhH[j] = 0.f;
    }
    for (size_t j = i; j < (size_t)Bz * Hz; j += stride) {
        g_hsum[j] = 0.f; g_hprev[j] = 0.f;
    }
    if (i == 0) { g_bar_count = 0u; g_bar_gen = 0u; }
}

// ---- P1: Gx = embed[x] @ {Wix,Wfx,Wux}^T + bias (unchanged, known-good) ----
__global__ __launch_bounds__(256) void k_precompute(
    const int* __restrict__ x, const float* __restrict__ embed,
    const float* __restrict__ Wix, const float* __restrict__ bix,
    const float* __restrict__ Wfx, const float* __restrict__ bfx,
    const float* __restrict__ Wux, const float* __restrict__ bux)
{
    const int nt = blockIdx.x;            // 0..23
    const int mt = blockIdx.y;            // 0..127
    const int g  = nt >> 3;
    const int jbase = (nt & 7) * 64;
    const float* W    = (g == 0) ? Wix : (g == 1) ? Wfx : Wux;
    const float* bias = (g == 0) ? bix : (g == 1) ? bfx : bux;
    const int tid = threadIdx.x;

    __shared__ int wid[64];
    __shared__ __align__(16) float As[16][64];
    __shared__ __align__(16) float Bs[16][64];

    const int rowbase = mt * 64;
    if (tid < 64) wid[tid] = x[rowbase + tid];
    __syncthreads();

    const int sm  = tid >> 2;
    const int skq = tid & 3;
    const int tm  = tid >> 4;
    const int tn  = tid & 15;

    unsigned long long acc[4][2];
#pragma unroll
    for (int r = 0; r < 4; r++) { acc[r][0] = 0ull; acc[r][1] = 0ull; }

    for (int kc = 0; kc < 19; kc++) {
        const int k = kc * 16 + skq * 4;
        float4 va = make_float4(0.f,0.f,0.f,0.f), vb = va;
        if (k < Ez) {
            va = *reinterpret_cast<const float4*>(&embed[(size_t)wid[sm] * Ez + k]);
            vb = *reinterpret_cast<const float4*>(&W[(size_t)(jbase + sm) * Ez + k]);
        }
        As[skq*4+0][sm]=va.x; As[skq*4+1][sm]=va.y; As[skq*4+2][sm]=va.z; As[skq*4+3][sm]=va.w;
        Bs[skq*4+0][sm]=vb.x; Bs[skq*4+1][sm]=vb.y; Bs[skq*4+2][sm]=vb.z; Bs[skq*4+3][sm]=vb.w;
        __syncthreads();
#pragma unroll
        for (int kk = 0; kk < 16; kk++) {
            const float4 a4 = *reinterpret_cast<const float4*>(&As[kk][tm * 4]);
            const ulonglong2 bv = *reinterpret_cast<const ulonglong2*>(&Bs[kk][tn * 4]);
            const unsigned long long a0 = pk2(a4.x, a4.x);
            const unsigned long long a1 = pk2(a4.y, a4.y);
            const unsigned long long a2 = pk2(a4.z, a4.z);
            const unsigned long long a3 = pk2(a4.w, a4.w);
            acc[0][0]=fma2(a0,bv.x,acc[0][0]); acc[0][1]=fma2(a0,bv.y,acc[0][1]);
            acc[1][0]=fma2(a1,bv.x,acc[1][0]); acc[1][1]=fma2(a1,bv.y,acc[1][1]);
            acc[2][0]=fma2(a2,bv.x,acc[2][0]); acc[2][1]=fma2(a2,bv.y,acc[2][1]);
            acc[3][0]=fma2(a3,bv.x,acc[3][0]); acc[3][1]=fma2(a3,bv.y,acc[3][1]);
        }
        __syncthreads();
    }

    const int j = jbase + tn * 4;
#pragma unroll
    for (int r = 0; r < 4; r++) {
        const int row = rowbase + tm * 4 + r;
        float* dst = &g_Gx[(size_t)row * GXW + g * Hz + j];
        const float2 p0 = upk2(acc[r][0]);
        const float2 p1 = upk2(acc[r][1]);
        dst[0] = p0.x + bias[j+0]; dst[1] = p0.y + bias[j+1];
        dst[2] = p1.x + bias[j+2]; dst[3] = p1.y + bias[j+3];
    }
}

// ---- grid-wide sense barrier ------------------------------------------------
static __device__ __forceinline__ void gridbar(unsigned int& gen) {
    __syncthreads();
    if (threadIdx.x == 0) {
        __threadfence();
        unsigned int a = atomicAdd(&g_bar_count, 1u);
        if (a == NBLK - 1) {
            g_bar_count = 0u;
            __threadfence();
            atomicExch(&g_bar_gen, gen + 1u);
        } else {
            while (atomicAdd(&g_bar_gen, 0u) <= gen) { }
        }
        __threadfence();
    }
    gen++;
    __syncthreads();
}

// ---- persistent recurrence kernel ------------------------------------------
// smem: Wp [512][32] u64 pairs (128KB) | As [2][64][64] f (32KB) | small area
#define SM_WP   0
#define SM_AS   131072
#define SM_SMALL 163840
#define SMEM_TOTAL (163840 + 1024)

extern __shared__ unsigned char smem_raw[];

__global__ __launch_bounds__(NTHR, 1) void k_recur(
    const int* __restrict__ bfs, const int* __restrict__ children,
    const float* __restrict__ Wih, const float* __restrict__ Wfh,
    const float* __restrict__ Wuh,
    const float* __restrict__ bih, const float* __restrict__ bfh,
    const float* __restrict__ buh,
    const float* __restrict__ Wout, const float* __restrict__ bout,
    float* __restrict__ out)
{
    const int blk = blockIdx.x;          // batch id AND gemm tile id
    const int tid = threadIdx.x;

    unsigned long long* Wp = (unsigned long long*)(smem_raw + SM_WP);
    float* As = (float*)(smem_raw + SM_AS);
    unsigned char* sb = smem_raw + SM_SMALL;
    int*   s_bfs  = (int*)sb;                          // 64 ints
    unsigned char* m0 = sb + 256;                      // 64
    unsigned char* m1 = sb + 320;                      // 64
    short* l0 = (short*)(sb + 384);                    // 64
    short* l1 = (short*)(sb + 512);                    // 64
    int*   s_n = (int*)(sb + 640);                     // n0, n1
    unsigned long long* s_mask = (unsigned long long*)(sb + 648);

    // GEMM tile assignment
    const int mt = blk >> 6;             // 0..1  -> rows [mt*64, +64)
    const int nt = blk & 63;             // 0..63 -> cols [nt*32, +32)
    const int colbase = nt * 32;
    const int g = colbase >> 9;          // gate id 0..3
    const int wrow0 = colbase & 511;
    const float* Wsrc = (g == 0) ? Wih : (g == 2) ? Wuh : Wfh;
    const int m0row = mt * 64;

    // One-time smem fill: W pairs (conflict-free STS; L1-friendly LDG)
    for (int i = tid; i < 32 * 512; i += NTHR) {
        const int c = i & 31, k = i >> 5;
        const float w = Wsrc[(size_t)(wrow0 + c) * Hz + k];
        Wp[(size_t)k * 32 + c] = pk2(w, w);
    }
    if (tid < Sz) s_bfs[tid] = bfs[blk * Sz + tid];
    if (tid == 0) *s_mask = 0ull;
    const float vbih = bih[tid], vbfh = bfh[tid], vbuh = buh[tid];
    __syncthreads();

    // compute-warp geometry (warps 0..3)
    const int wz = tid >> 5, lane = tid & 31;
    const int wr = (wz >> 1) & 1, wc = wz & 1;
    const int lr = lane >> 2,     lc = lane & 3;
    const int rloc = wr * 32 + lr * 4;              // row in [0,64)
    const int cloc = wc * 16 + lc * 4;              // col in [0,32)

    unsigned int gen = 0;

    for (int t = 0; t < Sz; t++) {
        // ===================== GEMM phase =====================
        const float* Asrc = (g == 3) ? g_hprev : g_hsum;

        // stage chunk 0 (all threads)
        for (int i = tid; i < 1024; i += NTHR) {
            const int row = i >> 4, kq = i & 15;
            const float4 v = *reinterpret_cast<const float4*>(
                &Asrc[(size_t)(m0row + row) * Hz + kq * 4]);
            const int rS = row ^ ((kq & 15) << 2);          // xor swizzle
            float* d = &As[(kq * 4) * 64 + rS];
            d[0] = v.x; d[64] = v.y; d[128] = v.z; d[192] = v.w;
        }
        __syncthreads();

        unsigned long long acc[2][4];
#pragma unroll
        for (int c = 0; c < 4; c++) { acc[0][c] = 0ull; acc[1][c] = 0ull; }

        for (int kc = 0; kc < 8; kc++) {
            const int cur = kc & 1;
            if (wz >= 4) {
                if (kc < 7) {
                    const int nb = (cur ^ 1) * 4096;
                    for (int i = tid - 128; i < 1024; i += 384) {
                        const int row = i >> 4, kq = i & 15;
                        const float4 v = *reinterpret_cast<const float4*>(
                            &Asrc[(size_t)(m0row + row) * Hz + (kc + 1) * 64 + kq * 4]);
                        const int rS = row ^ ((kq & 15) << 2);
                        float* d = &As[nb + (kq * 4) * 64 + rS];
                        d[0] = v.x; d[64] = v.y; d[128] = v.z; d[192] = v.w;
                    }
                }
            } else {
                const float* Ab = &As[cur * 4096];
                const unsigned long long* Wb = &Wp[(size_t)(kc * 64) * 32];
#pragma unroll 16
                for (int kk = 0; kk < 64; kk++) {
                    const int v = ((kk >> 2) & 15) << 2;
                    const ulonglong2 ar = *reinterpret_cast<const ulonglong2*>(
                        &Ab[kk * 64 + (rloc ^ v)]);
                    const ulonglong2 w01 = *reinterpret_cast<const ulonglong2*>(
                        &Wb[kk * 32 + cloc]);
                    const ulonglong2 w23 = *reinterpret_cast<const ulonglong2*>(
                        &Wb[kk * 32 + cloc + 2]);
                    acc[0][0] = fma2(ar.x, w01.x, acc[0][0]);
                    acc[1][0] = fma2(ar.y, w01.x, acc[1][0]);
                    acc[0][1] = fma2(ar.x, w01.y, acc[0][1]);
                    acc[1][1] = fma2(ar.y, w01.y, acc[1][1]);
                    acc[0][2] = fma2(ar.x, w23.x, acc[0][2]);
                    acc[1][2] = fma2(ar.y, w23.x, acc[1][2]);
                    acc[0][3] = fma2(ar.x, w23.y, acc[0][3]);
                    acc[1][3] = fma2(ar.y, w23.y, acc[1][3]);
                }
            }
            __syncthreads();
        }

        if (wz < 4) {
            const int grow = m0row + rloc;
            const int gcol = colbase + cloc;
#pragma unroll
            for (int c = 0; c < 4; c++) {
                const float2 p0 = upk2(acc[0][c]);
                const float2 p1 = upk2(acc[1][c]);
                g_y[(size_t)(grow + 0) * 2048 + gcol + c] = p0.x;
                g_y[(size_t)(grow + 1) * 2048 + gcol + c] = p0.y;
                g_y[(size_t)(grow + 2) * 2048 + gcol + c] = p1.x;
                g_y[(size_t)(grow + 3) * 2048 + gcol + c] = p1.y;
            }
        }
        __threadfence();
        gridbar(gen);

        // ===================== gates phase (block = batch) =====================
        const int cur  = s_bfs[t];
        const int prev = (t > 0)      ? s_bfs[t - 1] : -1;
        const int nxt  = (t < Sz - 1) ? s_bfs[t + 1] : -1;

        if (tid < Sz)
            m0[tid] = (unsigned char)(children[((size_t)blk * Sz + cur) * Sz + tid] != 0);
        if (nxt >= 0 && tid >= Sz && tid < 2 * Sz)
            m1[tid - Sz] = (unsigned char)(children[((size_t)blk * Sz + nxt) * Sz + (tid - Sz)] != 0);
        __syncthreads();

        if (tid == 0) {
            const unsigned long long bits = *s_mask;
            const unsigned long long b2 = bits | (1ull << cur);
            int c0 = 0, c1 = 0;
            for (int s = 0; s < Sz; s++) {
                if (m0[s] && ((bits >> s) & 1ull)) l0[c0++] = (short)s;
                if (nxt >= 0 && m1[s] && ((b2 >> s) & 1ull)) l1[c1++] = (short)s;
            }
            s_n[0] = c0; s_n[1] = c1; *s_mask = b2;
        }
        __syncthreads();

        const int h = tid;
        const float* gx = &g_Gx[(size_t)(blk * Sz + cur) * GXW];
        const float gxi = gx[h], gxf = gx[Hz + h], gxu = gx[2 * Hz + h];
        const float* yb = &g_y[(size_t)blk * 2048];
        const float yi = yb[h], yo = yb[Hz + h], yu = yb[2 * Hz + h], y4 = yb[3 * Hz + h];

        const float ig = sigm(gxi + yi + vbih);
        const float og = sigm(gxf + yo + vbfh);       // faithful: 'o' uses fx/fh
        const float ug = tanhf(gxu + yu + vbuh);

        const float base = gxf + vbfh;
        const size_t bh = (size_t)blk * Sz * Hz + h;
        const int n0 = s_n[0], n1 = s_n[1];

        float fc = 0.f;
        int i2 = 0;
        for (; i2 + 1 < n0; i2 += 2) {
            const int s0 = l0[i2], s1 = l0[i2 + 1];
            const float wf0 = (s0 == prev) ? y4 : g_WfhH[bh + (size_t)s0 * Hz];
            const float C0  = g_allC[bh + (size_t)s0 * Hz];
            const float wf1 = (s1 == prev) ? y4 : g_WfhH[bh + (size_t)s1 * Hz];
            const float C1  = g_allC[bh + (size_t)s1 * Hz];
            fc += sigm(wf0 + base) * C0;
            fc += sigm(wf1 + base) * C1;
        }
        if (i2 < n0) {
            const int s0 = l0[i2];
            const float wf0 = (s0 == prev) ? y4 : g_WfhH[bh + (size_t)s0 * Hz];
            fc += sigm(wf0 + base) * g_allC[bh + (size_t)s0 * Hz];
        }

        const float cc = ig * ug + fc;
        const float hn = og * tanhf(cc);

        g_allC[bh + (size_t)cur * Hz] = cc;
        g_allH[bh + (size_t)cur * Hz] = hn;
        if (prev >= 0) g_WfhH[bh + (size_t)prev * Hz] = y4;
        g_hprev[blk * Hz + h] = hn;

        if (nxt >= 0) {
            float hs = 0.f;
            for (int j = 0; j < n1; j++) {
                const int s = l1[j];
                hs += (s == cur) ? hn : g_allH[bh + (size_t)s * Hz];
            }
            g_hsum[blk * Hz + h] = hs;
        }
        __threadfence();
        gridbar(gen);
    }

    // ===================== output head =====================
    if (tid < 32 * Lz) {
        const int w = tid >> 5, ln = tid & 31;
        float p = 0.f;
        for (int hh = ln; hh < Hz; hh += 32)
            p += g_hprev[blk * Hz + hh] * Wout[w * Hz + hh];
#pragma unroll
        for (int o = 16; o; o >>= 1) p += __shfl_down_sync(0xffffffffu, p, o);
        if (ln == 0) out[blk * Lz + w] = p + bout[w];
    }
}

// ---- launch ----------------------------------------------------------------
extern "C" void kernel_launch(void* const* d_in, const int* in_sizes, int n_in,
                              void* d_out, int out_size) {
    const int*   x        = (const int*)d_in[0];
    const int*   bfs      = (const int*)d_in[1];
    const int*   children = (const int*)d_in[2];
    const float* embed    = (const float*)d_in[3];
    const float* Wix = (const float*)d_in[4],  *bix = (const float*)d_in[5];
    const float* Wih = (const float*)d_in[6],  *bih = (const float*)d_in[7];
    const float* Wfx = (const float*)d_in[8],  *bfx = (const float*)d_in[9];
    const float* Wfh = (const float*)d_in[10], *bfh = (const float*)d_in[11];
    const float* Wux = (const float*)d_in[12], *bux = (const float*)d_in[13];
    const float* Wuh = (const float*)d_in[14], *buh = (const float*)d_in[15];
    const float* Wout = (const float*)d_in[16], *bout = (const float*)d_in[17];
    float* out = (float*)d_out;

    static bool attr_set = false;
    if (!attr_set) {
        cudaFuncSetAttribute(k_recur, cudaFuncAttributeMaxDynamicSharedMemorySize,
                             SMEM_TOTAL);
        attr_set = true;
    }

    k_init<<<1024, 256>>>();
    k_precompute<<<dim3(24, 128), 256>>>(x, embed, Wix, bix, Wfx, bfx, Wux, bux);
    k_recur<<<NBLK, NTHR, SMEM_TOTAL>>>(bfs, children, Wih, Wfh, Wuh,
                                        bih, bfh, buh, Wout, bout, out);
}